// round 1
// baseline (speedup 1.0000x reference)
#include <cuda_runtime.h>

#define N_NODES 20000
#define N_EDGES 150000
#define FEAT 64
#define HEADS 8
#define NRBF 20
#define OUTD 512          // HEADS*FEAT
#define CUTOFF 5.0f
#define PI_F 3.14159265358979323846f

// Node-level Q/K projection tables (scratch; __device__ globals are the
// sanctioned way to get scratch without allocating).
__device__ float g_Q[(size_t)N_NODES * OUTD];
__device__ float g_K[(size_t)N_NODES * OUTD];

typedef unsigned long long u64;

__device__ __forceinline__ u64 pack2(float lo, float hi) {
    u64 r; asm("mov.b64 %0, {%1, %2};" : "=l"(r) : "f"(lo), "f"(hi)); return r;
}
__device__ __forceinline__ void unpack2(u64 v, float& lo, float& hi) {
    asm("mov.b64 {%0, %1}, %2;" : "=f"(lo), "=f"(hi) : "l"(v));
}
// packed fp32x2 FMA: 2 fp32 MACs per issue slot (sm_100+)
__device__ __forceinline__ u64 ffma2(u64 a, u64 b, u64 c) {
    u64 d; asm("fma.rn.f32x2 %0, %1, %2, %3;" : "=l"(d) : "l"(a), "l"(b), "l"(c)); return d;
}
__device__ __forceinline__ float silu_f(float x) {
    return __fdividef(x, 1.0f + __expf(-x));
}

// ============================================================================
// Kernel 1: node projections  Q[n,o] = sum_f x[n,f]*W[o,f] + b[o]
// (W_q flat [h][g][f] row-major == [o=h*64+g][f], so it is already [512][64])
// Tile: 128 nodes x 64 outputs, 256 threads, 4x8 micro-tile, K paired in f32x2.
// ============================================================================
#define PM 128
#define PN 64
#define SSTR 66   // smem row stride (floats): even (8B aligned) and /2 odd -> conflict-free

__global__ void __launch_bounds__(256, 2)
proj_kernel(const float* __restrict__ x,
            const float* __restrict__ Wq, const float* __restrict__ bq,
            const float* __restrict__ Wk, const float* __restrict__ bk)
{
    extern __shared__ float sm[];
    float* Xs = sm;                // [128][SSTR]
    float* Ws = sm + PM * SSTR;    // [64][SSTR]

    const float* W = blockIdx.z ? Wk : Wq;
    const float* b = blockIdx.z ? bk : bq;
    float* out     = blockIdx.z ? g_K : g_Q;

    const int t  = threadIdx.x;
    const int m0 = blockIdx.x * PM;
    const int n0 = blockIdx.y * PN;

    // ---- load X tile (128 x 64 floats) ----
    #pragma unroll
    for (int p = 0; p < 8; p++) {
        int idx = t + p * 256;                 // 2048 float4s
        int ml = idx >> 4, fs = (idx & 15) << 2;
        int node = m0 + ml;
        float4 v = make_float4(0.f, 0.f, 0.f, 0.f);
        if (node < N_NODES)
            v = *reinterpret_cast<const float4*>(x + (size_t)node * FEAT + fs);
        float* dst = Xs + ml * SSTR + fs;
        dst[0] = v.x; dst[1] = v.y; dst[2] = v.z; dst[3] = v.w;
    }
    // ---- load W tile (64 x 64 floats) ----
    #pragma unroll
    for (int p = 0; p < 4; p++) {
        int idx = t + p * 256;                 // 1024 float4s
        int nl = idx >> 4, fs = (idx & 15) << 2;
        float4 v = *reinterpret_cast<const float4*>(W + (size_t)(n0 + nl) * FEAT + fs);
        float* dst = Ws + nl * SSTR + fs;
        dst[0] = v.x; dst[1] = v.y; dst[2] = v.z; dst[3] = v.w;
    }
    __syncthreads();

    const int tx = t & 7;    // output group (interleaved: n = j*8 + tx)
    const int ty = t >> 3;   // node group   (interleaved: m = i*32 + ty)

    u64 acc[4][8];           // (even-f sum, odd-f sum) pairs
    #pragma unroll
    for (int i = 0; i < 4; i++)
        #pragma unroll
        for (int j = 0; j < 8; j++) acc[i][j] = 0ULL;

    #pragma unroll 4
    for (int fp = 0; fp < 32; fp++) {
        u64 x2[4], w2[8];
        #pragma unroll
        for (int i = 0; i < 4; i++)
            x2[i] = *reinterpret_cast<const u64*>(Xs + (i * 32 + ty) * SSTR + 2 * fp);
        #pragma unroll
        for (int j = 0; j < 8; j++)
            w2[j] = *reinterpret_cast<const u64*>(Ws + (j * 8 + tx) * SSTR + 2 * fp);
        #pragma unroll
        for (int i = 0; i < 4; i++)
            #pragma unroll
            for (int j = 0; j < 8; j++)
                acc[i][j] = ffma2(x2[i], w2[j], acc[i][j]);
    }

    #pragma unroll
    for (int i = 0; i < 4; i++) {
        int node = m0 + i * 32 + ty;
        if (node < N_NODES) {
            #pragma unroll
            for (int j = 0; j < 8; j++) {
                int n = j * 8 + tx;
                float lo, hi; unpack2(acc[i][j], lo, hi);
                out[(size_t)node * OUTD + n0 + n] = lo + hi + b[n0 + n];
            }
        }
    }
}

// ============================================================================
// Kernel 2: per-edge fused RBF + d_k matvec + q*k*d_k reduce + silu.
// 128 threads per edge (2 edges / 256-thread block). Thread owns head h = tt/16,
// f-quad f0 = (tt%16)*4. W_dk coefficients live in registers as f32x2 pairs
// (paired over r), loaded once and amortized over a grid-stride loop.
// ============================================================================
__global__ void __launch_bounds__(256, 2)
edge_kernel(const float* __restrict__ dist,
            const int* __restrict__ nbrs,
            const float* __restrict__ Wdk,
            const float* __restrict__ bdk,
            float* __restrict__ out)
{
    __shared__ __align__(16) float efs[2][NRBF];

    const int t     = threadIdx.x;
    const int eslot = t >> 7;       // which of the 2 edges in this block
    const int tt    = t & 127;      // thread-in-edge
    const int h     = tt >> 4;      // head 0..7
    const int sub   = tt & 15;      // 16 threads per head
    const int f0    = sub << 2;     // 4 consecutive f per thread
    const int row   = h * FEAT + f0;

    // persistent per-thread W_dk coefficients: 4 rows x 20 rbf, r-paired
    u64 W2[4][10];
    float br[4];
    #pragma unroll
    for (int p = 0; p < 4; p++) {
        br[p] = bdk[row + p];
        const float* wr = Wdk + (size_t)(row + p) * NRBF;   // rows are 80B -> 8B aligned
        #pragma unroll
        for (int r2 = 0; r2 < 10; r2++)
            W2[p][r2] = *reinterpret_cast<const u64*>(wr + 2 * r2);
    }

    const float thc = PI_F / CUTOFF;

    for (int base = blockIdx.x * 2; base < N_EDGES; base += gridDim.x * 2) {
        const int e = base + eslot;
        const int ni = nbrs[2 * e];
        const int nj = nbrs[2 * e + 1];
        // prefetch gathers early; latency hidden under RBF/sync
        const float4 qv = *reinterpret_cast<const float4*>(g_Q + (size_t)ni * OUTD + row);
        const float4 kv = *reinterpret_cast<const float4*>(g_K + (size_t)nj * OUTD + row);

        __syncthreads();  // previous iteration's efs readers are done
        if (tt < NRBF) {
            float d   = dist[e];
            float th  = d * thc;
            float env = (d < CUTOFF) ? 0.5f * (cosf(th) + 1.0f) : 0.0f;
            efs[eslot][tt] = sinf((float)(tt + 1) * th) * env / d;
        }
        __syncthreads();

        u64 ef2[10];
        #pragma unroll
        for (int r2 = 0; r2 < 10; r2++)
            ef2[r2] = *reinterpret_cast<const u64*>(&efs[eslot][2 * r2]);

        float s = 0.f;
        #pragma unroll
        for (int p = 0; p < 4; p++) {
            u64 a2 = pack2(br[p], 0.f);     // bias folded into the even lane
            #pragma unroll
            for (int r2 = 0; r2 < 10; r2++)
                a2 = ffma2(ef2[r2], W2[p][r2], a2);
            float lo, hi; unpack2(a2, lo, hi);
            float dk = silu_f(lo + hi);
            float q = (p == 0) ? qv.x : (p == 1) ? qv.y : (p == 2) ? qv.z : qv.w;
            float k = (p == 0) ? kv.x : (p == 1) ? kv.y : (p == 2) ? kv.z : kv.w;
            s += q * k * dk;
        }
        // reduce the 16 sub-lanes of this head (contiguous within the warp)
        #pragma unroll
        for (int off = 8; off > 0; off >>= 1)
            s += __shfl_down_sync(0xffffffffu, s, off, 16);
        if (sub == 0)
            out[(size_t)e * HEADS + h] = silu_f(s);
    }
}

// ============================================================================
extern "C" void kernel_launch(void* const* d_in, const int* in_sizes, int n_in,
                              void* d_out, int out_size)
{
    (void)in_sizes; (void)n_in; (void)out_size;
    const float* dist = (const float*)d_in[0];
    const int*   nbrs = (const int*)  d_in[1];
    const float* x_i  = (const float*)d_in[2];
    const float* W_q  = (const float*)d_in[3];
    const float* b_q  = (const float*)d_in[4];
    const float* W_k  = (const float*)d_in[5];
    const float* b_k  = (const float*)d_in[6];
    const float* W_dk = (const float*)d_in[7];
    const float* b_dk = (const float*)d_in[8];
    float* out = (float*)d_out;

    const int smem = (PM * SSTR + PN * SSTR) * (int)sizeof(float);  // 50688 B
    cudaFuncSetAttribute(proj_kernel, cudaFuncAttributeMaxDynamicSharedMemorySize, smem);

    dim3 pg((N_NODES + PM - 1) / PM, OUTD / PN, 2);   // (157, 8, 2)
    proj_kernel<<<pg, 256, smem>>>(x_i, W_q, b_q, W_k, b_k);
    edge_kernel<<<592, 256>>>(dist, nbrs, W_dk, b_dk, out);
}

// round 2
// speedup vs baseline: 1.9124x; 1.9124x over previous
#include <cuda_runtime.h>
#include <cuda_fp16.h>

#define N_NODES 20000
#define N_EDGES 150000
#define FEAT 64
#define HEADS 8
#define NRBF 20
#define OUTD 512          // HEADS*FEAT
#define CUTOFF 5.0f
#define PI_F 3.14159265358979323846f

// Node-level Q/K projection tables in fp16 (halves gather traffic + wavefronts).
__device__ __half g_Qh[(size_t)N_NODES * OUTD];
__device__ __half g_Kh[(size_t)N_NODES * OUTD];

typedef unsigned long long u64;

__device__ __forceinline__ u64 pack2(float lo, float hi) {
    u64 r; asm("mov.b64 %0, {%1, %2};" : "=l"(r) : "f"(lo), "f"(hi)); return r;
}
__device__ __forceinline__ void unpack2(u64 v, float& lo, float& hi) {
    asm("mov.b64 {%0, %1}, %2;" : "=f"(lo), "=f"(hi) : "l"(v));
}
// packed fp32x2 FMA: 2 fp32 MACs per issue slot
__device__ __forceinline__ u64 ffma2(u64 a, u64 b, u64 c) {
    u64 d; asm("fma.rn.f32x2 %0, %1, %2, %3;" : "=l"(d) : "l"(a), "l"(b), "l"(c)); return d;
}
__device__ __forceinline__ float silu_f(float x) {
    return __fdividef(x, 1.0f + __expf(-x));
}

// ============================================================================
// Kernel 1: node projections  Q[n,o] = sum_f x[n,f]*W[o,f] + b[o], fp16 out.
// 128x64 tile, 256 threads, 4x8 micro-tile, K paired in f32x2.
// SMEM uses stride-64 rows with XOR-rotation swizzle: col' = (col + 4*(row&7))&63
// -> conflict-free LDS.64 for both the ty-strided X reads and tx-strided W reads.
// ============================================================================
#define PM 128
#define PN 64

__device__ __forceinline__ int swz(int row, int col) {
    return row * 64 + ((col + 4 * (row & 7)) & 63);
}

__global__ void __launch_bounds__(256, 2)
proj_kernel(const float* __restrict__ x,
            const float* __restrict__ Wq, const float* __restrict__ bq,
            const float* __restrict__ Wk, const float* __restrict__ bk)
{
    extern __shared__ float sm[];
    float* Xs = sm;             // [128][64] swizzled
    float* Ws = sm + PM * 64;   // [64][64] swizzled

    const float* W = blockIdx.z ? Wk : Wq;
    const float* b = blockIdx.z ? bk : bq;
    __half* out    = blockIdx.z ? g_Kh : g_Qh;

    const int t  = threadIdx.x;
    const int m0 = blockIdx.x * PM;
    const int n0 = blockIdx.y * PN;

    // ---- load X tile (128 x 64 floats) ----
    #pragma unroll
    for (int p = 0; p < 8; p++) {
        int idx = t + p * 256;                 // 2048 float4s
        int ml = idx >> 4, fs = (idx & 15) << 2;
        int node = m0 + ml;
        float4 v = make_float4(0.f, 0.f, 0.f, 0.f);
        if (node < N_NODES)
            v = *reinterpret_cast<const float4*>(x + (size_t)node * FEAT + fs);
        *reinterpret_cast<float4*>(Xs + swz(ml, fs)) = v;
    }
    // ---- load W tile (64 x 64 floats) ----
    #pragma unroll
    for (int p = 0; p < 4; p++) {
        int idx = t + p * 256;                 // 1024 float4s
        int nl = idx >> 4, fs = (idx & 15) << 2;
        float4 v = *reinterpret_cast<const float4*>(W + (size_t)(n0 + nl) * FEAT + fs);
        *reinterpret_cast<float4*>(Ws + swz(nl, fs)) = v;
    }
    __syncthreads();

    const int tx = t & 7;    // output group (n = j*8 + tx)
    const int ty = t >> 3;   // node group   (m = i*32 + ty)

    float bn[8];
    #pragma unroll
    for (int j = 0; j < 8; j++) bn[j] = b[n0 + j * 8 + tx];

    u64 acc[4][8];
    #pragma unroll
    for (int i = 0; i < 4; i++)
        #pragma unroll
        for (int j = 0; j < 8; j++) acc[i][j] = 0ULL;

    #pragma unroll 4
    for (int fp = 0; fp < 32; fp++) {
        u64 x2[4], w2[8];
        #pragma unroll
        for (int i = 0; i < 4; i++)
            x2[i] = *reinterpret_cast<const u64*>(Xs + swz(i * 32 + ty, 2 * fp));
        #pragma unroll
        for (int j = 0; j < 8; j++)
            w2[j] = *reinterpret_cast<const u64*>(Ws + swz(j * 8 + tx, 2 * fp));
        #pragma unroll
        for (int i = 0; i < 4; i++)
            #pragma unroll
            for (int j = 0; j < 8; j++)
                acc[i][j] = ffma2(x2[i], w2[j], acc[i][j]);
    }

    #pragma unroll
    for (int i = 0; i < 4; i++) {
        int node = m0 + i * 32 + ty;
        if (node < N_NODES) {
            #pragma unroll
            for (int j = 0; j < 8; j++) {
                float lo, hi; unpack2(acc[i][j], lo, hi);
                out[(size_t)node * OUTD + n0 + j * 8 + tx] =
                    __float2half_rn(lo + hi + bn[j]);
            }
        }
    }
}

// ============================================================================
// Kernel 2: thread-per-edge, warp-synchronous. W_dk staged in SMEM; all lanes
// walk (h,f) in lockstep so every W_dk LDS.64 is a 32-way broadcast (1 phase).
// RBF via Chebyshev recurrence from one __sincosf. q/k gathered as fp16 uint4.
// ============================================================================
#define EB 256

__global__ void __launch_bounds__(EB, 3)
edge_kernel(const float* __restrict__ dist,
            const int* __restrict__ nbrs,
            const float* __restrict__ Wdk,
            const float* __restrict__ bdk,
            float* __restrict__ out)
{
    __shared__ __align__(16) float sW[OUTD * NRBF];  // 40 KB, rows of 20 (80B, 8B-aligned)
    __shared__ float sB[OUTD];                       // 2 KB

    const int t = threadIdx.x;
    for (int i = t * 4; i < OUTD * NRBF; i += EB * 4)
        *reinterpret_cast<float4*>(sW + i) = *reinterpret_cast<const float4*>(Wdk + i);
    for (int i = t; i < OUTD; i += EB)
        sB[i] = bdk[i];
    __syncthreads();

    for (int e = blockIdx.x * EB + t; e < N_EDGES; e += gridDim.x * EB) {
        const int2 nb = reinterpret_cast<const int2*>(nbrs)[e];
        const float d = dist[e];

        // edge_feats: ef[n-1] = sin(n*theta)*env/d, theta = pi*d/5, env = 0.5(cos theta + 1)
        float s1, c1;
        __sincosf(d * (PI_F / CUTOFF), &s1, &c1);
        const float eod = (d < CUTOFF) ? __fdividef(0.5f * (c1 + 1.0f), d) : 0.0f;
        const float c2 = 2.0f * c1;

        u64 ef2[NRBF / 2];
        {
            float sm2 = 0.0f, sm1 = s1;
            #pragma unroll
            for (int r = 0; r < NRBF / 2; r++) {
                float ea = sm1 * eod;
                float sn = c2 * sm1 - sm2;  sm2 = sm1;  sm1 = sn;
                float eb = sm1 * eod;
                sn = c2 * sm1 - sm2;        sm2 = sm1;  sm1 = sn;
                ef2[r] = pack2(ea, eb);
            }
        }

        const uint4* qrow = reinterpret_cast<const uint4*>(g_Qh + (size_t)nb.x * OUTD);
        const uint4* krow = reinterpret_cast<const uint4*>(g_Kh + (size_t)nb.y * OUTD);

        float w8[HEADS];
        #pragma unroll 1
        for (int h = 0; h < HEADS; h++) {
            float acc = 0.0f;
            const float* wrow = sW + h * (FEAT * NRBF);
            const float* brow = sB + h * FEAT;
            #pragma unroll 1
            for (int c = 0; c < 8; c++) {           // 8 fp16 per uint4
                const uint4 qv = qrow[h * 8 + c];
                const uint4 kv = krow[h * 8 + c];
                const unsigned int qw[4] = {qv.x, qv.y, qv.z, qv.w};
                const unsigned int kw[4] = {kv.x, kv.y, kv.z, kv.w};
                #pragma unroll
                for (int m = 0; m < 4; m++) {
                    const float2 qf = __half22float2(*reinterpret_cast<const __half2*>(&qw[m]));
                    const float2 kf = __half22float2(*reinterpret_cast<const __half2*>(&kw[m]));
                    const int f0 = c * 8 + m * 2;
                    const float* wr = wrow + f0 * NRBF;
                    u64 a2 = 0ULL, b2 = 0ULL;
                    #pragma unroll
                    for (int r = 0; r < NRBF / 2; r++) {
                        a2 = ffma2(ef2[r], *reinterpret_cast<const u64*>(wr + 2 * r), a2);
                        b2 = ffma2(ef2[r], *reinterpret_cast<const u64*>(wr + NRBF + 2 * r), b2);
                    }
                    float lo, hi;
                    unpack2(a2, lo, hi);
                    float dk0 = silu_f(lo + hi + brow[f0]);
                    unpack2(b2, lo, hi);
                    float dk1 = silu_f(lo + hi + brow[f0 + 1]);
                    acc = fmaf(qf.x * kf.x, dk0, acc);
                    acc = fmaf(qf.y * kf.y, dk1, acc);
                }
            }
            w8[h] = silu_f(acc);
        }

        float4* o4 = reinterpret_cast<float4*>(out + (size_t)e * HEADS);
        o4[0] = make_float4(w8[0], w8[1], w8[2], w8[3]);
        o4[1] = make_float4(w8[4], w8[5], w8[6], w8[7]);
    }
}

// ============================================================================
extern "C" void kernel_launch(void* const* d_in, const int* in_sizes, int n_in,
                              void* d_out, int out_size)
{
    (void)in_sizes; (void)n_in; (void)out_size;
    const float* dist = (const float*)d_in[0];
    const int*   nbrs = (const int*)  d_in[1];
    const float* x_i  = (const float*)d_in[2];
    const float* W_q  = (const float*)d_in[3];
    const float* b_q  = (const float*)d_in[4];
    const float* W_k  = (const float*)d_in[5];
    const float* b_k  = (const float*)d_in[6];
    const float* W_dk = (const float*)d_in[7];
    const float* b_dk = (const float*)d_in[8];
    float* out = (float*)d_out;

    const int smem = (PM * 64 + PN * 64) * (int)sizeof(float);  // 49152 B
    cudaFuncSetAttribute(proj_kernel, cudaFuncAttributeMaxDynamicSharedMemorySize, smem);

    dim3 pg((N_NODES + PM - 1) / PM, OUTD / PN, 2);   // (157, 8, 2)
    proj_kernel<<<pg, 256, smem>>>(x_i, W_q, b_q, W_k, b_k);

    const int eblocks = (N_EDGES + EB - 1) / EB;      // 586
    edge_kernel<<<eblocks, EB>>>(dist, nbrs, W_dk, b_dk, out);
}

// round 4
// speedup vs baseline: 2.2260x; 1.1640x over previous
#include <cuda_runtime.h>
#include <cuda_fp16.h>

#define N_NODES 20000
#define N_EDGES 150000
#define FEAT 64
#define HEADS 8
#define NRBF 20
#define OUTD 512          // HEADS*FEAT
#define CUTOFF 5.0f
#define PI_F 3.14159265358979323846f

// Node-level Q/K projection tables in fp16.
__device__ __half g_Qh[(size_t)N_NODES * OUTD];
__device__ __half g_Kh[(size_t)N_NODES * OUTD];

typedef unsigned long long u64;

__device__ __forceinline__ u64 pack2(float lo, float hi) {
    u64 r; asm("mov.b64 %0, {%1, %2};" : "=l"(r) : "f"(lo), "f"(hi)); return r;
}
__device__ __forceinline__ void unpack2(u64 v, float& lo, float& hi) {
    asm("mov.b64 {%0, %1}, %2;" : "=f"(lo), "=f"(hi) : "l"(v));
}
// packed fp32x2 FMA: 2 fp32 MACs per issue slot
__device__ __forceinline__ u64 ffma2(u64 a, u64 b, u64 c) {
    u64 d; asm("fma.rn.f32x2 %0, %1, %2, %3;" : "=l"(d) : "l"(a), "l"(b), "l"(c)); return d;
}
__device__ __forceinline__ float silu_f(float x) {
    return __fdividef(x, 1.0f + __expf(-x));
}

// ============================================================================
// Kernel 1: node projections  Q[n,o] = sum_f x[n,f]*W[o,f] + b[o], fp16 out.
// 128x64 tile, 256 threads, 4x8 micro-tile, K paired in f32x2.
// Xs swizzle keyed on (row&7) (reader rows stride 32 -> ty&7 varies);
// Ws swizzle keyed on ((row>>3)&7) (reader rows = tx*8+j -> tx varies).
// Outputs per thread are 8 consecutive n -> uint2 fp16 epilogue stores.
// ============================================================================
#define PM 128
#define PN 64

__device__ __forceinline__ int swzX(int row, int col) {
    return row * 64 + ((col + 4 * (row & 7)) & 63);
}
__device__ __forceinline__ int swzW(int row, int col) {
    return row * 64 + ((col + 4 * ((row >> 3) & 7)) & 63);
}

__global__ void __launch_bounds__(256, 2)
proj_kernel(const float* __restrict__ x,
            const float* __restrict__ Wq, const float* __restrict__ bq,
            const float* __restrict__ Wk, const float* __restrict__ bk)
{
    extern __shared__ float sm[];
    float* Xs = sm;             // [128][64] swizzled (X)
    float* Ws = sm + PM * 64;   // [64][64] swizzled (W)

    const float* W = blockIdx.z ? Wk : Wq;
    const float* b = blockIdx.z ? bk : bq;
    __half* out    = blockIdx.z ? g_Kh : g_Qh;

    const int t  = threadIdx.x;
    const int m0 = blockIdx.x * PM;
    const int n0 = blockIdx.y * PN;

    #pragma unroll
    for (int p = 0; p < 8; p++) {
        int idx = t + p * 256;                 // 2048 float4s
        int ml = idx >> 4, fs = (idx & 15) << 2;
        int node = m0 + ml;
        float4 v = make_float4(0.f, 0.f, 0.f, 0.f);
        if (node < N_NODES)
            v = *reinterpret_cast<const float4*>(x + (size_t)node * FEAT + fs);
        *reinterpret_cast<float4*>(Xs + swzX(ml, fs)) = v;
    }
    #pragma unroll
    for (int p = 0; p < 4; p++) {
        int idx = t + p * 256;                 // 1024 float4s
        int nl = idx >> 4, fs = (idx & 15) << 2;
        float4 v = *reinterpret_cast<const float4*>(W + (size_t)(n0 + nl) * FEAT + fs);
        *reinterpret_cast<float4*>(Ws + swzW(nl, fs)) = v;
    }
    __syncthreads();

    const int tx = t & 7;    // output group: n = tx*8 + j (consecutive per thread)
    const int ty = t >> 3;   // node group:   m = i*32 + ty

    float bn[8];
    #pragma unroll
    for (int j = 0; j < 8; j++) bn[j] = b[n0 + tx * 8 + j];

    u64 acc[4][8];
    #pragma unroll
    for (int i = 0; i < 4; i++)
        #pragma unroll
        for (int j = 0; j < 8; j++) acc[i][j] = 0ULL;

    #pragma unroll 4
    for (int fp = 0; fp < 32; fp++) {
        u64 x2[4], w2[8];
        #pragma unroll
        for (int i = 0; i < 4; i++)
            x2[i] = *reinterpret_cast<const u64*>(Xs + swzX(i * 32 + ty, 2 * fp));
        #pragma unroll
        for (int j = 0; j < 8; j++)
            w2[j] = *reinterpret_cast<const u64*>(Ws + swzW(tx * 8 + j, 2 * fp));
        #pragma unroll
        for (int i = 0; i < 4; i++)
            #pragma unroll
            for (int j = 0; j < 8; j++)
                acc[i][j] = ffma2(x2[i], w2[j], acc[i][j]);
    }

    #pragma unroll
    for (int i = 0; i < 4; i++) {
        int node = m0 + i * 32 + ty;
        if (node < N_NODES) {
            float v[8];
            #pragma unroll
            for (int j = 0; j < 8; j++) {
                float lo, hi; unpack2(acc[i][j], lo, hi);
                v[j] = lo + hi + bn[j];
            }
            __half2 h01 = __floats2half2_rn(v[0], v[1]);
            __half2 h23 = __floats2half2_rn(v[2], v[3]);
            __half2 h45 = __floats2half2_rn(v[4], v[5]);
            __half2 h67 = __floats2half2_rn(v[6], v[7]);
            __half* dst = out + (size_t)node * OUTD + n0 + tx * 8;
            uint2 lo4 = make_uint2(*(unsigned*)&h01, *(unsigned*)&h23);
            uint2 hi4 = make_uint2(*(unsigned*)&h45, *(unsigned*)&h67);
            *reinterpret_cast<uint2*>(dst)     = lo4;
            *reinterpret_cast<uint2*>(dst + 4) = hi4;
        }
    }
}

// ============================================================================
// Kernel 2: 2 edges per thread, warp-synchronous lockstep over (h,c,m) so all
// W_dk SMEM reads are full-warp broadcasts. W streamed via LDS.128 (rows f0 and
// f0+1 are 10 consecutive float4), each chunk reused for 4 ffma2 (2 rows x 2
// edges). Bias folded into accumulator init. Grid covers all edges in 1 pass.
// ============================================================================
#define EB 256
#define EDGES_PER_BLOCK (2 * EB)

__global__ void __launch_bounds__(EB, 2)
edge_kernel(const float* __restrict__ dist,
            const int* __restrict__ nbrs,
            const float* __restrict__ Wdk,
            const float* __restrict__ bdk,
            float* __restrict__ out)
{
    __shared__ __align__(16) float sW[OUTD * NRBF];  // 40 KB
    __shared__ __align__(8)  float sB[OUTD];         // 2 KB

    const int t = threadIdx.x;
    for (int i = t * 4; i < OUTD * NRBF; i += EB * 4)
        *reinterpret_cast<float4*>(sW + i) = *reinterpret_cast<const float4*>(Wdk + i);
    for (int i = t; i < OUTD; i += EB)
        sB[i] = bdk[i];
    __syncthreads();

    const int e0 = blockIdx.x * EDGES_PER_BLOCK + t;     // always < N_EDGES
    const int e1 = e0 + EB;
    const bool v1 = (e1 < N_EDGES);
    const int eb = v1 ? e1 : e0;

    const int2 nA = reinterpret_cast<const int2*>(nbrs)[e0];
    const int2 nB = reinterpret_cast<const int2*>(nbrs)[eb];
    const float dA = dist[e0];
    const float dB = dist[eb];

    // RBF via Chebyshev recurrence: ef[n-1] = sin(n*theta)*env/d
    u64 ef2a[NRBF / 2], ef2b[NRBF / 2];
    {
        float s1, c1;
        __sincosf(dA * (PI_F / CUTOFF), &s1, &c1);
        const float eod = (dA < CUTOFF) ? __fdividef(0.5f * (c1 + 1.0f), dA) : 0.0f;
        const float c2 = 2.0f * c1;
        float sm2 = 0.0f, sm1 = s1;
        #pragma unroll
        for (int r = 0; r < NRBF / 2; r++) {
            float ea = sm1 * eod;
            float sn = c2 * sm1 - sm2;  sm2 = sm1;  sm1 = sn;
            float ebv = sm1 * eod;
            sn = c2 * sm1 - sm2;        sm2 = sm1;  sm1 = sn;
            ef2a[r] = pack2(ea, ebv);
        }
    }
    {
        float s1, c1;
        __sincosf(dB * (PI_F / CUTOFF), &s1, &c1);
        const float eod = (dB < CUTOFF) ? __fdividef(0.5f * (c1 + 1.0f), dB) : 0.0f;
        const float c2 = 2.0f * c1;
        float sm2 = 0.0f, sm1 = s1;
        #pragma unroll
        for (int r = 0; r < NRBF / 2; r++) {
            float ea = sm1 * eod;
            float sn = c2 * sm1 - sm2;  sm2 = sm1;  sm1 = sn;
            float ebv = sm1 * eod;
            sn = c2 * sm1 - sm2;        sm2 = sm1;  sm1 = sn;
            ef2b[r] = pack2(ea, ebv);
        }
    }

    const uint4* qA = reinterpret_cast<const uint4*>(g_Qh + (size_t)nA.x * OUTD);
    const uint4* kA = reinterpret_cast<const uint4*>(g_Kh + (size_t)nA.y * OUTD);
    const uint4* qB = reinterpret_cast<const uint4*>(g_Qh + (size_t)nB.x * OUTD);
    const uint4* kB = reinterpret_cast<const uint4*>(g_Kh + (size_t)nB.y * OUTD);

    float w8a[HEADS], w8b[HEADS];

    #pragma unroll 1
    for (int h = 0; h < HEADS; h++) {
        float accA = 0.0f, accB = 0.0f;
        const float4*  wh = reinterpret_cast<const float4*>(sW + h * (FEAT * NRBF));
        const float2*  bh = reinterpret_cast<const float2*>(sB + h * FEAT);
        #pragma unroll 1
        for (int c = 0; c < 8; c++) {
            const uint4 qva = qA[h * 8 + c];
            const uint4 kva = kA[h * 8 + c];
            const uint4 qvb = qB[h * 8 + c];
            const uint4 kvb = kB[h * 8 + c];
            const unsigned qwa[4] = {qva.x, qva.y, qva.z, qva.w};
            const unsigned kwa[4] = {kva.x, kva.y, kva.z, kva.w};
            const unsigned qwb[4] = {qvb.x, qvb.y, qvb.z, qvb.w};
            const unsigned kwb[4] = {kvb.x, kvb.y, kvb.z, kvb.w};
            #pragma unroll
            for (int m = 0; m < 4; m++) {
                const int f0 = c * 8 + 2 * m;
                const float4* wr = wh + f0 * 5;        // rows f0, f0+1: 10 float4
                const float2  bb = bh[c * 4 + m];      // b[f0], b[f0+1]

                u64 zA = pack2(bb.x, 0.f), zB = pack2(bb.x, 0.f);   // row f0
                u64 yA = pack2(bb.y, 0.f), yB = pack2(bb.y, 0.f);   // row f0+1
                #pragma unroll
                for (int j = 0; j < 5; j++) {
                    const float4 w = wr[j];
                    const u64 wlo = pack2(w.x, w.y);
                    const u64 whi = pack2(w.z, w.w);
                    zA = ffma2(ef2a[2 * j], wlo, zA);
                    zA = ffma2(ef2a[2 * j + 1], whi, zA);
                    zB = ffma2(ef2b[2 * j], wlo, zB);
                    zB = ffma2(ef2b[2 * j + 1], whi, zB);
                }
                #pragma unroll
                for (int j = 0; j < 5; j++) {
                    const float4 w = wr[5 + j];
                    const u64 wlo = pack2(w.x, w.y);
                    const u64 whi = pack2(w.z, w.w);
                    yA = ffma2(ef2a[2 * j], wlo, yA);
                    yA = ffma2(ef2a[2 * j + 1], whi, yA);
                    yB = ffma2(ef2b[2 * j], wlo, yB);
                    yB = ffma2(ef2b[2 * j + 1], whi, yB);
                }

                float lo, hi;
                unpack2(zA, lo, hi); const float dkA0 = silu_f(lo + hi);
                unpack2(yA, lo, hi); const float dkA1 = silu_f(lo + hi);
                unpack2(zB, lo, hi); const float dkB0 = silu_f(lo + hi);
                unpack2(yB, lo, hi); const float dkB1 = silu_f(lo + hi);

                const float2 qa = __half22float2(*reinterpret_cast<const __half2*>(&qwa[m]));
                const float2 ka = __half22float2(*reinterpret_cast<const __half2*>(&kwa[m]));
                const float2 qb = __half22float2(*reinterpret_cast<const __half2*>(&qwb[m]));
                const float2 kb = __half22float2(*reinterpret_cast<const __half2*>(&kwb[m]));

                accA = fmaf(qa.x * ka.x, dkA0, accA);
                accA = fmaf(qa.y * ka.y, dkA1, accA);
                accB = fmaf(qb.x * kb.x, dkB0, accB);
                accB = fmaf(qb.y * kb.y, dkB1, accB);
            }
        }
        w8a[h] = silu_f(accA);
        w8b[h] = silu_f(accB);
    }

    float4* oa = reinterpret_cast<float4*>(out + (size_t)e0 * HEADS);
    oa[0] = make_float4(w8a[0], w8a[1], w8a[2], w8a[3]);
    oa[1] = make_float4(w8a[4], w8a[5], w8a[6], w8a[7]);
    if (v1) {
        float4* ob = reinterpret_cast<float4*>(out + (size_t)e1 * HEADS);
        ob[0] = make_float4(w8b[0], w8b[1], w8b[2], w8b[3]);
        ob[1] = make_float4(w8b[4], w8b[5], w8b[6], w8b[7]);
    }
}

// ============================================================================
extern "C" void kernel_launch(void* const* d_in, const int* in_sizes, int n_in,
                              void* d_out, int out_size)
{
    (void)in_sizes; (void)n_in; (void)out_size;
    const float* dist = (const float*)d_in[0];
    const int*   nbrs = (const int*)  d_in[1];
    const float* x_i  = (const float*)d_in[2];
    const float* W_q  = (const float*)d_in[3];
    const float* b_q  = (const float*)d_in[4];
    const float* W_k  = (const float*)d_in[5];
    const float* b_k  = (const float*)d_in[6];
    const float* W_dk = (const float*)d_in[7];
    const float* b_dk = (const float*)d_in[8];
    float* out = (float*)d_out;

    const int smem = (PM * 64 + PN * 64) * (int)sizeof(float);  // 49152 B
    cudaFuncSetAttribute(proj_kernel, cudaFuncAttributeMaxDynamicSharedMemorySize, smem);

    dim3 pg((N_NODES + PM - 1) / PM, OUTD / PN, 2);   // (157, 8, 2)
    proj_kernel<<<pg, 256, smem>>>(x_i, W_q, b_q, W_k, b_k);

    const int eblocks = (N_EDGES + EDGES_PER_BLOCK - 1) / EDGES_PER_BLOCK;  // 293
    edge_kernel<<<eblocks, EB>>>(dist, nbrs, W_dk, b_dk, out);
}